// round 15
// baseline (speedup 1.0000x reference)
#include <cuda_runtime.h>
#include <cuda_fp16.h>
#include <cstdint>

#define NUM_TAGS 9
#define DDIM 64
#define HID 768
#define SEQ 512
#define BATCH 16
#define NQK (NUM_TAGS * 2 * DDIM)   /* 1152 */
#define MASKV 1e12f

// Scratch (fp16 everywhere)
__device__ __half g_Q[(size_t)BATCH * NUM_TAGS * SEQ * DDIM];
__device__ __half g_K[(size_t)BATCH * NUM_TAGS * SEQ * DDIM];
__device__ __half g_ench[(size_t)BATCH * SEQ * HID];
__device__ __half g_Wt[(size_t)NQK * HID];                       // W^T [n][k]
__device__ float2 g_rope[SEQ * 32];                              // (sin,cos) per (s,pair)

__device__ __forceinline__ uint32_t smem_u32(const void* p) {
    uint32_t a;
    asm("{ .reg .u64 t; cvta.to.shared.u64 t, %1; cvt.u32.u64 %0, t; }" : "=r"(a) : "l"(p));
    return a;
}
__device__ __forceinline__ void cpasync16s(uint32_t saddr, const void* g) {
    asm volatile("cp.async.cg.shared.global [%0], [%1], 16;\n" :: "r"(saddr), "l"(g));
}
#define CP_COMMIT() asm volatile("cp.async.commit_group;\n")
#define SW128(o) ((o) ^ (((o) >> 3) & 0x70))

__device__ __forceinline__ void mma16816h(uint32_t* c, const uint32_t* a, const uint32_t* b) {
    asm volatile(
        "mma.sync.aligned.m16n8k16.row.col.f16.f16.f16.f16 "
        "{%0,%1}, {%2,%3,%4,%5}, {%6,%7}, {%0,%1};\n"
        : "+r"(c[0]), "+r"(c[1])
        : "r"(a[0]), "r"(a[1]), "r"(a[2]), "r"(a[3]), "r"(b[0]), "r"(b[1]));
}
__device__ __forceinline__ void ldsm_x4(uint32_t addr, uint32_t* r) {
    asm volatile("ldmatrix.sync.aligned.m8n8.x4.shared.b16 {%0,%1,%2,%3}, [%4];"
        : "=r"(r[0]), "=r"(r[1]), "=r"(r[2]), "=r"(r[3]) : "r"(addr));
}
__device__ __forceinline__ void stcs128(float* g, float4 v) {
    asm volatile("st.global.cs.v4.f32 [%0], {%1,%2,%3,%4};"
        :: "l"(g), "f"(v.x), "f"(v.y), "f"(v.z), "f"(v.w) : "memory");
}

// ===================== Merged prep kernel =====================
__global__ __launch_bounds__(256) void prep_all(
    const float* __restrict__ enc, __half* __restrict__ ench,
    const float* __restrict__ W, __half* __restrict__ Wt,
    float2* __restrict__ rope)
{
    __shared__ __half t[64][72];
    const int b = blockIdx.x;
    const int tid = threadIdx.x;

    if (b < 1536) {
        const int NV = BATCH * SEQ * HID / 4;
        for (int i = b * 256 + tid; i < NV; i += 1536 * 256) {
            float4 v = *(const float4*)(enc + (size_t)i * 4);
            __half2 lo = __floats2half2_rn(v.x, v.y);
            __half2 hi = __floats2half2_rn(v.z, v.w);
            uint2 o = { *(unsigned*)&lo, *(unsigned*)&hi };
            *(uint2*)(ench + (size_t)i * 4) = o;
        }
    } else if (b < 1536 + 216) {
        const int w = b - 1536;
        const int kb = (w % 12) * 64, nb = (w / 12) * 64;
        #pragma unroll
        for (int it = 0; it < 4; ++it) {
            int idx = tid + it * 256;
            int r = idx >> 4, c4 = (idx & 15) * 4;
            float4 v = *(const float4*)(W + (size_t)(kb + r) * NQK + nb + c4);
            t[c4 + 0][r] = __float2half_rn(v.x);
            t[c4 + 1][r] = __float2half_rn(v.y);
            t[c4 + 2][r] = __float2half_rn(v.z);
            t[c4 + 3][r] = __float2half_rn(v.w);
        }
        __syncthreads();
        #pragma unroll
        for (int it = 0; it < 4; ++it) {
            int idx = tid + it * 256;
            int r = idx >> 4, c4 = (idx & 15) * 4;
            *(uint2*)(Wt + (size_t)(nb + r) * HID + kb + c4) = *(uint2*)&t[r][c4];
        }
    } else {
        int i = (b - 1752) * 256 + tid;
        if (i < SEQ * 32) {
            int s = i >> 5, p = i & 31;
            const float LN1E4_OVER_32 = 0.28782313662425572f;
            float inv = expf(-(float)p * LN1E4_OVER_32);
            float sv, cv;
            sincosf((float)s * inv, &sv, &cv);
            rope[i] = make_float2(sv, cv);
        }
    }
}

// ===================== Kernel A: GEMM1 + bias + RoPE + masked-tile fill ======
// CTA tile 128(M) x 128(N = one tag). 8 warps = 2(M) x 4(N); warp tile 64x32.
// K-tile 64 (SW128), 2-stage cp.async, fp16 in / f16 acc.
// Launched per 3-tag chunk: grid (64, 3), tag = tagbase + blockIdx.y.
#define G1_KT 64
#define G1_NT (HID / G1_KT)          /* 12 */
#define G1_ASZ (128 * 128)           /* 16KB */
#define G1_STAGE (2 * G1_ASZ)        /* 32KB */
#define G1_DYN (2 * G1_STAGE + 256)

__global__ __launch_bounds__(256, 2) void gemm1_rope(
    const float* __restrict__ bias, const int* __restrict__ amask,
    float* __restrict__ out, int tagbase)
{
    extern __shared__ char dyn_raw[];
    const uint32_t dsm = (smem_u32(dyn_raw) + 127) & ~127u;
    __shared__ float s_bias[128];

    const int tid  = threadIdx.x;
    const int lane = tid & 31, wid = tid >> 5;
    const int warp_m = wid & 1;
    const int warp_n = wid >> 1;
    const int g  = lane >> 2;
    const int t4 = lane & 3;

    const int m0 = blockIdx.x * 128;
    const int tag = tagbase + blockIdx.y;
    const int n0 = tag * 128;

    if (tid < 128) s_bias[tid] = bias[n0 + tid];

    const __half* Ag = g_ench + (size_t)m0 * HID;
    const __half* Bg = g_Wt   + (size_t)n0 * HID;

    uint32_t acc[4][4][2];
    #pragma unroll
    for (int mi = 0; mi < 4; ++mi)
        #pragma unroll
        for (int ni = 0; ni < 4; ++ni) { acc[mi][ni][0] = 0u; acc[mi][ni][1] = 0u; }

    auto load_tile = [&](int kt, int st) {
        const int k0 = kt * G1_KT;
        const uint32_t abase = dsm + st * G1_STAGE;
        const uint32_t bbase = abase + G1_ASZ;
        #pragma unroll
        for (int i = 0; i < 4; ++i) {
            int idx = tid + i * 256;
            int r = idx >> 3, c = idx & 7;
            uint32_t off = (uint32_t)(r * 128 + c * 16);
            cpasync16s(abase + SW128(off), Ag + (size_t)r * HID + k0 + c * 8);
        }
        #pragma unroll
        for (int i = 0; i < 4; ++i) {
            int idx = tid + i * 256;
            int r = idx >> 3, c = idx & 7;
            uint32_t off = (uint32_t)(r * 128 + c * 16);
            cpasync16s(bbase + SW128(off), Bg + (size_t)r * HID + k0 + c * 8);
        }
    };

    load_tile(0, 0); CP_COMMIT();
    load_tile(1, 1); CP_COMMIT();

    // ---- Causal-masked output tile fill (independent of GEMM; DRAM idle) ----
    {
        const int cid = tag * 64 + blockIdx.x;            // 0..575 across chunks
        const int ST[6] = {1, 2, 2, 3, 3, 3};
        const int TT[6] = {0, 0, 1, 0, 1, 2};
        #pragma unroll 4
        for (int k_ = 0; k_ < 24; ++k_) {
            int idx = cid * 6144 + k_ * 256 + tid;
            int tile_id = idx >> 12;
            int within = idx & 4095;
            int row = within >> 5, c4 = (within & 31) << 2;
            int bh = tile_id / 6, mt = tile_id - bh * 6;
            int bidx2 = bh / NUM_TAGS;
            int s0 = ST[mt] * 128, t0 = TT[mt] * 128;
            int4 mv = *(const int4*)(amask + bidx2 * SEQ + t0 + c4);
            float4 o;
            o.x = ((float)mv.x - 2.0f) * 1.25e11f;
            o.y = ((float)mv.y - 2.0f) * 1.25e11f;
            o.z = ((float)mv.z - 2.0f) * 1.25e11f;
            o.w = ((float)mv.w - 2.0f) * 1.25e11f;
            stcs128(out + ((size_t)bh * SEQ + s0 + row) * SEQ + t0 + c4, o);
        }
    }

    const uint32_t aK = ((lane >> 4) << 3) * 2;
    const uint32_t bK = (((lane >> 3) & 1) << 3) * 2;

    for (int kt = 0; kt < G1_NT; ++kt) {
        const int st = kt & 1;
        if (kt + 1 < G1_NT) asm volatile("cp.async.wait_group 1;\n" ::: "memory");
        else                asm volatile("cp.async.wait_group 0;\n" ::: "memory");
        __syncthreads();

        const uint32_t abase = dsm + st * G1_STAGE;
        const uint32_t bbase = abase + G1_ASZ;

        uint32_t arb[4], axv[4];
        #pragma unroll
        for (int mi = 0; mi < 4; ++mi) {
            int r = warp_m * 64 + mi * 16 + (lane & 15);
            arb[mi] = abase + r * 128;
            axv[mi] = (r & 7) << 4;
        }
        uint32_t brb[2], bxv[2];
        #pragma unroll
        for (int nj = 0; nj < 2; ++nj) {
            int n = warp_n * 32 + nj * 16 + ((lane >> 4) << 3) + (lane & 7);
            brb[nj] = bbase + n * 128;
            bxv[nj] = (n & 7) << 4;
        }

        #pragma unroll
        for (int kk2 = 0; kk2 < 128; kk2 += 32) {
            uint32_t a[4][4], b[2][4];
            #pragma unroll
            for (int mi = 0; mi < 4; ++mi)
                ldsm_x4(arb[mi] + ((kk2 + aK) ^ axv[mi]), a[mi]);
            #pragma unroll
            for (int nj = 0; nj < 2; ++nj)
                ldsm_x4(brb[nj] + ((kk2 + bK) ^ bxv[nj]), b[nj]);
            #pragma unroll
            for (int mi = 0; mi < 4; ++mi) {
                #pragma unroll
                for (int ni = 0; ni < 4; ++ni)
                    mma16816h(acc[mi][ni], a[mi], &b[ni >> 1][(ni & 1) * 2]);
            }
        }
        __syncthreads();
        if (kt + 2 < G1_NT) { load_tile(kt + 2, st); CP_COMMIT(); }
    }

    // ---- Epilogue: bias + RoPE -> fp16 Q/K ----
    #pragma unroll
    for (int ni = 0; ni < 4; ++ni) {
        const int col = warp_n * 32 + ni * 8 + t4 * 2;
        const bool isq = col < 64;
        const int dcol = col & 63;
        const float b0 = s_bias[col], b1 = s_bias[col + 1];
        __half* dstbase = isq ? g_Q : g_K;
        #pragma unroll
        for (int mi = 0; mi < 4; ++mi) {
            #pragma unroll
            for (int rr = 0; rr < 2; ++rr) {
                const int m = m0 + warp_m * 64 + mi * 16 + g + rr * 8;
                const int bb = m >> 9, s = m & 511;
                float2 sc = g_rope[s * 32 + (dcol >> 1)];
                __half2 hv = *(__half2*)&acc[mi][ni][rr];
                float v0 = __low2float(hv) + b0;
                float v1 = __high2float(hv) + b1;
                float y0 = v0 * sc.y - v1 * sc.x;
                float y1 = v1 * sc.y + v0 * sc.x;
                size_t off = (((size_t)(bb * NUM_TAGS + tag) * SEQ + s) * DDIM + dcol);
                *(__half2*)(dstbase + off) = __floats2half2_rn(y0, y1);
            }
        }
    }
}

// ===================== Kernel B: QK^T + mask + scale (upper tiles only) ======
// Launched per 3-tag chunk: grid (10, 48); y -> (bidx = y/3, tag = tagbase + y%3).
__global__ __launch_bounds__(512, 2) void gemm2_mask(
    const int* __restrict__ amask, float* __restrict__ out, int tagbase)
{
    const int ST2[10] = {0, 1, 2, 3, 0, 0, 0, 1, 1, 2};
    const int TT2[10] = {0, 1, 2, 3, 1, 2, 3, 2, 3, 3};
    const int st = ST2[blockIdx.x], tt = TT2[blockIdx.x];
    const int y = blockIdx.y;
    const int bidx = y / 3;
    const int tag = tagbase + (y - bidx * 3);
    const int bh = bidx * NUM_TAGS + tag;
    const int t0 = tt * 128, s0 = st * 128;
    const int tid = threadIdx.x;

    __shared__ __align__(16) char sraw[36864];
    __half (*Qs)[72] = (__half (*)[72])sraw;
    __half (*Ks)[72] = (__half (*)[72])(sraw + 18432);
    float (*SF)[132] = (float (*)[132])sraw;

    const __half* Qg = g_Q + ((size_t)bh * SEQ + s0) * DDIM;
    const __half* Kg = g_K + ((size_t)bh * SEQ + t0) * DDIM;
    #pragma unroll
    for (int it = 0; it < 2; ++it) {
        int idx = tid + it * 512;
        int r = idx >> 3, c8 = (idx & 7) * 8;
        *(uint4*)&Qs[r][c8] = *(const uint4*)(Qg + (size_t)r * DDIM + c8);
        *(uint4*)&Ks[r][c8] = *(const uint4*)(Kg + (size_t)r * DDIM + c8);
    }
    __syncthreads();

    const int lane = tid & 31, wid = tid >> 5;
    const int warp_m = wid & 3, warp_n = wid >> 2;
    const int g = lane >> 2, t4 = lane & 3;

    uint32_t acc[2][4][2];
    #pragma unroll
    for (int mi = 0; mi < 2; ++mi)
        #pragma unroll
        for (int ni = 0; ni < 4; ++ni) { acc[mi][ni][0] = 0u; acc[mi][ni][1] = 0u; }

    const uint32_t qbase = smem_u32(&Qs[0][0]);
    const uint32_t kbase = smem_u32(&Ks[0][0]);
    uint32_t arb[2], brb[2];
    #pragma unroll
    for (int mi = 0; mi < 2; ++mi) {
        int r = warp_m * 32 + mi * 16 + (lane & 15);
        arb[mi] = qbase + r * 144 + ((lane >> 4) << 4);
    }
    #pragma unroll
    for (int nj = 0; nj < 2; ++nj) {
        int n = warp_n * 32 + nj * 16 + ((lane >> 4) << 3) + (lane & 7);
        brb[nj] = kbase + n * 144 + (((lane >> 3) & 1) << 4);
    }

    #pragma unroll
    for (int kk = 0; kk < 64; kk += 16) {
        uint32_t a[2][4], b[2][4];
        #pragma unroll
        for (int mi = 0; mi < 2; ++mi)
            ldsm_x4(arb[mi] + kk * 2, a[mi]);
        #pragma unroll
        for (int nj = 0; nj < 2; ++nj)
            ldsm_x4(brb[nj] + kk * 2, b[nj]);
        #pragma unroll
        for (int mi = 0; mi < 2; ++mi)
            #pragma unroll
            for (int ni = 0; ni < 4; ++ni)
                mma16816h(acc[mi][ni], a[mi], &b[ni >> 1][(ni & 1) * 2]);
    }

    __syncthreads();

    #pragma unroll
    for (int h = 0; h < 2; ++h) {
        if ((warp_m >> 1) == h) {
            const int rbase = (warp_m & 1) * 32;
            #pragma unroll
            for (int ni = 0; ni < 4; ++ni) {
                const int cl = warp_n * 32 + ni * 8 + t4 * 2;
                #pragma unroll
                for (int mi = 0; mi < 2; ++mi) {
                    #pragma unroll
                    for (int rr = 0; rr < 2; ++rr) {
                        const int rl = rbase + mi * 16 + g + rr * 8;
                        __half2 hv = *(__half2*)&acc[mi][ni][rr];
                        SF[rl][cl]     = __low2float(hv);
                        SF[rl][cl + 1] = __high2float(hv);
                    }
                }
            }
        }
        __syncthreads();
        #pragma unroll
        for (int it = 0; it < 4; ++it) {
            int idx = tid + it * 512;
            int r = idx >> 5, c16 = (idx & 31) * 4;
            int row = s0 + h * 64 + r;
            int4 mv = *(const int4*)(amask + bidx * SEQ + t0 + c16);
            float4 v = *(const float4*)&SF[r][c16];
            float p;
            p = (float)mv.x; v.x = (v.x * p - (1.f - p) * MASKV - ((t0 + c16     < row) ? MASKV : 0.f)) * 0.125f;
            p = (float)mv.y; v.y = (v.y * p - (1.f - p) * MASKV - ((t0 + c16 + 1 < row) ? MASKV : 0.f)) * 0.125f;
            p = (float)mv.z; v.z = (v.z * p - (1.f - p) * MASKV - ((t0 + c16 + 2 < row) ? MASKV : 0.f)) * 0.125f;
            p = (float)mv.w; v.w = (v.w * p - (1.f - p) * MASKV - ((t0 + c16 + 3 < row) ? MASKV : 0.f)) * 0.125f;
            stcs128(out + ((size_t)bh * SEQ + row) * SEQ + t0 + c16, v);
        }
        if (h == 0) __syncthreads();
    }
}

extern "C" void kernel_launch(void* const* d_in, const int* in_sizes, int n_in,
                              void* d_out, int out_size) {
    (void)in_sizes; (void)n_in; (void)out_size;
    const float* enc  = (const float*)d_in[0];
    const int*   am   = (const int*)d_in[2];
    const float* W    = (const float*)d_in[3];
    const float* bias = (const float*)d_in[4];
    float* out = (float*)d_out;

    __half* ench; cudaGetSymbolAddress((void**)&ench, g_ench);
    __half* Wt;   cudaGetSymbolAddress((void**)&Wt,   g_Wt);
    float2* rope; cudaGetSymbolAddress((void**)&rope, g_rope);

    cudaFuncSetAttribute(gemm1_rope, cudaFuncAttributeMaxDynamicSharedMemorySize, G1_DYN);

    // Two-stream tag-chunk pipeline (graph-capture-legal fork/join via events).
    // kernel_launch is invoked only a couple of times (correctness + capture),
    // so creating the stream/events here does not grow with replay count.
    cudaStream_t s2;
    cudaStreamCreateWithFlags(&s2, cudaStreamNonBlocking);
    cudaEvent_t ev[3], evJoin;
    for (int k = 0; k < 3; ++k) cudaEventCreateWithFlags(&ev[k], cudaEventDisableTiming);
    cudaEventCreateWithFlags(&evJoin, cudaEventDisableTiming);

    prep_all<<<1816, 256>>>(enc, ench, W, Wt, rope);

    for (int k = 0; k < 3; ++k) {
        gemm1_rope<<<dim3(64, 3), 256, G1_DYN>>>(bias, am, out, 3 * k);
        cudaEventRecord(ev[k], 0);
        cudaStreamWaitEvent(s2, ev[k], 0);
        gemm2_mask<<<dim3(10, 48), 512, 0, s2>>>(am, out, 3 * k);
    }
    cudaEventRecord(evJoin, s2);
    cudaStreamWaitEvent(0, evJoin, 0);
}

// round 16
// speedup vs baseline: 1.2464x; 1.2464x over previous
#include <cuda_runtime.h>
#include <cuda_fp16.h>
#include <cstdint>

#define NUM_TAGS 9
#define DDIM 64
#define HID 768
#define SEQ 512
#define BATCH 16
#define NQK (NUM_TAGS * 2 * DDIM)   /* 1152 */
#define MASKV 1e12f

// Scratch (fp16 everywhere)
__device__ __half g_Q[(size_t)BATCH * NUM_TAGS * SEQ * DDIM];
__device__ __half g_K[(size_t)BATCH * NUM_TAGS * SEQ * DDIM];
__device__ __half g_ench[(size_t)BATCH * SEQ * HID];
__device__ __half g_Wt[(size_t)NQK * HID];                       // W^T [n][k]
__device__ float2 g_rope[SEQ * 32];                              // (sin,cos) per (s,pair)

__device__ __forceinline__ uint32_t smem_u32(const void* p) {
    uint32_t a;
    asm("{ .reg .u64 t; cvta.to.shared.u64 t, %1; cvt.u32.u64 %0, t; }" : "=r"(a) : "l"(p));
    return a;
}
__device__ __forceinline__ void cpasync16s(uint32_t saddr, const void* g) {
    asm volatile("cp.async.cg.shared.global [%0], [%1], 16;\n" :: "r"(saddr), "l"(g));
}
#define CP_COMMIT() asm volatile("cp.async.commit_group;\n")
#define SW128(o) ((o) ^ (((o) >> 3) & 0x70))

__device__ __forceinline__ void mma16816h(uint32_t* c, const uint32_t* a, const uint32_t* b) {
    asm volatile(
        "mma.sync.aligned.m16n8k16.row.col.f16.f16.f16.f16 "
        "{%0,%1}, {%2,%3,%4,%5}, {%6,%7}, {%0,%1};\n"
        : "+r"(c[0]), "+r"(c[1])
        : "r"(a[0]), "r"(a[1]), "r"(a[2]), "r"(a[3]), "r"(b[0]), "r"(b[1]));
}
__device__ __forceinline__ void ldsm_x4(uint32_t addr, uint32_t* r) {
    asm volatile("ldmatrix.sync.aligned.m8n8.x4.shared.b16 {%0,%1,%2,%3}, [%4];"
        : "=r"(r[0]), "=r"(r[1]), "=r"(r[2]), "=r"(r[3]) : "r"(addr));
}
__device__ __forceinline__ void stcs128(float* g, float4 v) {
    asm volatile("st.global.cs.v4.f32 [%0], {%1,%2,%3,%4};"
        :: "l"(g), "f"(v.x), "f"(v.y), "f"(v.z), "f"(v.w) : "memory");
}

// ===================== Merged prep kernel =====================
// [0,6144): enc fp32->fp16 one float4/thread ; [6144,6360): W tiles ; rest: rope
#define PREP_ENC_BLK 6144
#define PREP_BLKS (PREP_ENC_BLK + 216 + 64)

__global__ __launch_bounds__(256) void prep_all(
    const float* __restrict__ enc, __half* __restrict__ ench,
    const float* __restrict__ W, __half* __restrict__ Wt,
    float2* __restrict__ rope)
{
    __shared__ __half t[64][72];
    const int b = blockIdx.x;
    const int tid = threadIdx.x;

    if (b < PREP_ENC_BLK) {
        int i = b * 256 + tid;                       // exactly one float4 each
        float4 v = *(const float4*)(enc + (size_t)i * 4);
        __half2 lo = __floats2half2_rn(v.x, v.y);
        __half2 hi = __floats2half2_rn(v.z, v.w);
        uint2 o = { *(unsigned*)&lo, *(unsigned*)&hi };
        *(uint2*)(ench + (size_t)i * 4) = o;
    } else if (b < PREP_ENC_BLK + 216) {
        const int w = b - PREP_ENC_BLK;
        const int kb = (w % 12) * 64, nb = (w / 12) * 64;
        #pragma unroll
        for (int it = 0; it < 4; ++it) {
            int idx = tid + it * 256;
            int r = idx >> 4, c4 = (idx & 15) * 4;
            float4 v = *(const float4*)(W + (size_t)(kb + r) * NQK + nb + c4);
            t[c4 + 0][r] = __float2half_rn(v.x);
            t[c4 + 1][r] = __float2half_rn(v.y);
            t[c4 + 2][r] = __float2half_rn(v.z);
            t[c4 + 3][r] = __float2half_rn(v.w);
        }
        __syncthreads();
        #pragma unroll
        for (int it = 0; it < 4; ++it) {
            int idx = tid + it * 256;
            int r = idx >> 4, c4 = (idx & 15) * 4;
            *(uint2*)(Wt + (size_t)(nb + r) * HID + kb + c4) = *(uint2*)&t[r][c4];
        }
    } else {
        int i = (b - PREP_ENC_BLK - 216) * 256 + tid;
        if (i < SEQ * 32) {
            int s = i >> 5, p = i & 31;
            const float LN1E4_OVER_32 = 0.28782313662425572f;
            float inv = expf(-(float)p * LN1E4_OVER_32);
            float sv, cv;
            sincosf((float)s * inv, &sv, &cv);
            rope[i] = make_float2(sv, cv);
        }
    }
}

// ===================== Kernel A: GEMM1 + bias + RoPE + masked-tile fill ======
// (R10-best, unchanged) CTA tile 128x128, 8 warps 2x4, warp 64x32, fp16/f16acc.
#define G1_KT 64
#define G1_NT (HID / G1_KT)          /* 12 */
#define G1_ASZ (128 * 128)           /* 16KB */
#define G1_STAGE (2 * G1_ASZ)        /* 32KB */
#define G1_DYN (2 * G1_STAGE + 256)

__global__ __launch_bounds__(256, 2) void gemm1_rope(
    const float* __restrict__ bias, const int* __restrict__ amask,
    float* __restrict__ out)
{
    extern __shared__ char dyn_raw[];
    const uint32_t dsm = (smem_u32(dyn_raw) + 127) & ~127u;
    __shared__ float s_bias[128];

    const int tid  = threadIdx.x;
    const int lane = tid & 31, wid = tid >> 5;
    const int warp_m = wid & 1;
    const int warp_n = wid >> 1;
    const int g  = lane >> 2;
    const int t4 = lane & 3;

    const int m0 = blockIdx.x * 128;
    const int tag = blockIdx.y;
    const int n0 = tag * 128;

    if (tid < 128) s_bias[tid] = bias[n0 + tid];

    const __half* Ag = g_ench + (size_t)m0 * HID;
    const __half* Bg = g_Wt   + (size_t)n0 * HID;

    uint32_t acc[4][4][2];
    #pragma unroll
    for (int mi = 0; mi < 4; ++mi)
        #pragma unroll
        for (int ni = 0; ni < 4; ++ni) { acc[mi][ni][0] = 0u; acc[mi][ni][1] = 0u; }

    auto load_tile = [&](int kt, int st) {
        const int k0 = kt * G1_KT;
        const uint32_t abase = dsm + st * G1_STAGE;
        const uint32_t bbase = abase + G1_ASZ;
        #pragma unroll
        for (int i = 0; i < 4; ++i) {
            int idx = tid + i * 256;
            int r = idx >> 3, c = idx & 7;
            uint32_t off = (uint32_t)(r * 128 + c * 16);
            cpasync16s(abase + SW128(off), Ag + (size_t)r * HID + k0 + c * 8);
        }
        #pragma unroll
        for (int i = 0; i < 4; ++i) {
            int idx = tid + i * 256;
            int r = idx >> 3, c = idx & 7;
            uint32_t off = (uint32_t)(r * 128 + c * 16);
            cpasync16s(bbase + SW128(off), Bg + (size_t)r * HID + k0 + c * 8);
        }
    };

    load_tile(0, 0); CP_COMMIT();
    load_tile(1, 1); CP_COMMIT();

    // ---- Causal-masked output tile fill (independent of GEMM; DRAM idle) ----
    {
        const int cid = tag * 64 + blockIdx.x;            // 0..575
        const int ST[6] = {1, 2, 2, 3, 3, 3};
        const int TT[6] = {0, 0, 1, 0, 1, 2};
        #pragma unroll 4
        for (int k_ = 0; k_ < 24; ++k_) {
            int idx = cid * 6144 + k_ * 256 + tid;
            int tile_id = idx >> 12;
            int within = idx & 4095;
            int row = within >> 5, c4 = (within & 31) << 2;
            int bh = tile_id / 6, mt = tile_id - bh * 6;
            int bidx2 = bh / NUM_TAGS;
            int s0 = ST[mt] * 128, t0 = TT[mt] * 128;
            int4 mv = *(const int4*)(amask + bidx2 * SEQ + t0 + c4);
            float4 o;
            o.x = ((float)mv.x - 2.0f) * 1.25e11f;
            o.y = ((float)mv.y - 2.0f) * 1.25e11f;
            o.z = ((float)mv.z - 2.0f) * 1.25e11f;
            o.w = ((float)mv.w - 2.0f) * 1.25e11f;
            stcs128(out + ((size_t)bh * SEQ + s0 + row) * SEQ + t0 + c4, o);
        }
    }

    const uint32_t aK = ((lane >> 4) << 3) * 2;
    const uint32_t bK = (((lane >> 3) & 1) << 3) * 2;

    for (int kt = 0; kt < G1_NT; ++kt) {
        const int st = kt & 1;
        if (kt + 1 < G1_NT) asm volatile("cp.async.wait_group 1;\n" ::: "memory");
        else                asm volatile("cp.async.wait_group 0;\n" ::: "memory");
        __syncthreads();

        const uint32_t abase = dsm + st * G1_STAGE;
        const uint32_t bbase = abase + G1_ASZ;

        uint32_t arb[4], axv[4];
        #pragma unroll
        for (int mi = 0; mi < 4; ++mi) {
            int r = warp_m * 64 + mi * 16 + (lane & 15);
            arb[mi] = abase + r * 128;
            axv[mi] = (r & 7) << 4;
        }
        uint32_t brb[2], bxv[2];
        #pragma unroll
        for (int nj = 0; nj < 2; ++nj) {
            int n = warp_n * 32 + nj * 16 + ((lane >> 4) << 3) + (lane & 7);
            brb[nj] = bbase + n * 128;
            bxv[nj] = (n & 7) << 4;
        }

        #pragma unroll
        for (int kk2 = 0; kk2 < 128; kk2 += 32) {
            uint32_t a[4][4], b[2][4];
            #pragma unroll
            for (int mi = 0; mi < 4; ++mi)
                ldsm_x4(arb[mi] + ((kk2 + aK) ^ axv[mi]), a[mi]);
            #pragma unroll
            for (int nj = 0; nj < 2; ++nj)
                ldsm_x4(brb[nj] + ((kk2 + bK) ^ bxv[nj]), b[nj]);
            #pragma unroll
            for (int mi = 0; mi < 4; ++mi) {
                #pragma unroll
                for (int ni = 0; ni < 4; ++ni)
                    mma16816h(acc[mi][ni], a[mi], &b[ni >> 1][(ni & 1) * 2]);
            }
        }
        __syncthreads();
        if (kt + 2 < G1_NT) { load_tile(kt + 2, st); CP_COMMIT(); }
    }

    // ---- Epilogue: bias + RoPE -> fp16 Q/K ----
    #pragma unroll
    for (int ni = 0; ni < 4; ++ni) {
        const int col = warp_n * 32 + ni * 8 + t4 * 2;
        const bool isq = col < 64;
        const int dcol = col & 63;
        const float b0 = s_bias[col], b1 = s_bias[col + 1];
        __half* dstbase = isq ? g_Q : g_K;
        #pragma unroll
        for (int mi = 0; mi < 4; ++mi) {
            #pragma unroll
            for (int rr = 0; rr < 2; ++rr) {
                const int m = m0 + warp_m * 64 + mi * 16 + g + rr * 8;
                const int bb = m >> 9, s = m & 511;
                float2 sc = g_rope[s * 32 + (dcol >> 1)];
                __half2 hv = *(__half2*)&acc[mi][ni][rr];
                float v0 = __low2float(hv) + b0;
                float v1 = __high2float(hv) + b1;
                float y0 = v0 * sc.y - v1 * sc.x;
                float y1 = v1 * sc.y + v0 * sc.x;
                size_t off = (((size_t)(bb * NUM_TAGS + tag) * SEQ + s) * DDIM + dcol);
                *(__half2*)(dstbase + off) = __floats2half2_rn(y0, y1);
            }
        }
    }
}

// ===================== Kernel B: QK^T strips =====================
// grid (4, 144): st = strip, bh. Q tile loaded ONCE per strip; loop tt = st..3.
// smem: Qs (18KB, persistent) | tail region shared by Ks (18KB, mainloop)
// and SF staging (33.8KB, epilogue) — loop-top barrier protects the overlay.
#define G2_QSZ 18432
#define G2_DYN (G2_QSZ + 33792)      /* 52224 */

__global__ __launch_bounds__(512, 2) void gemm2_mask(
    const int* __restrict__ amask, float* __restrict__ out)
{
    extern __shared__ char dyn_raw[];
    __half (*Qs)[72] = (__half (*)[72])dyn_raw;
    __half (*Ks)[72] = (__half (*)[72])(dyn_raw + G2_QSZ);
    float (*SF)[132] = (float (*)[132])(dyn_raw + G2_QSZ);

    const int st = blockIdx.x;
    const int bh = blockIdx.y;
    const int bidx = bh / NUM_TAGS;
    const int s0 = st * 128;
    const int tid = threadIdx.x;
    const int lane = tid & 31, wid = tid >> 5;
    const int warp_m = wid & 3, warp_n = wid >> 2;
    const int g = lane >> 2, t4 = lane & 3;

    // Load Q strip once
    const __half* Qg = g_Q + ((size_t)bh * SEQ + s0) * DDIM;
    #pragma unroll
    for (int it = 0; it < 2; ++it) {
        int idx = tid + it * 512;
        int r = idx >> 3, c8 = (idx & 7) * 8;
        *(uint4*)&Qs[r][c8] = *(const uint4*)(Qg + (size_t)r * DDIM + c8);
    }

    // fragment addresses (fixed across tiles)
    const uint32_t qbase = smem_u32(&Qs[0][0]);
    const uint32_t kbase = smem_u32(&Ks[0][0]);
    uint32_t arb[2], brb[2];
    #pragma unroll
    for (int mi = 0; mi < 2; ++mi) {
        int r = warp_m * 32 + mi * 16 + (lane & 15);
        arb[mi] = qbase + r * 144 + ((lane >> 4) << 4);
    }
    #pragma unroll
    for (int nj = 0; nj < 2; ++nj) {
        int n = warp_n * 32 + nj * 16 + ((lane >> 4) << 3) + (lane & 7);
        brb[nj] = kbase + n * 144 + (((lane >> 3) & 1) << 4);
    }

    for (int tt = st; tt < 4; ++tt) {
        const int t0 = tt * 128;
        __syncthreads();   // prior SF consumed (and Q stores visible on 1st iter)

        const __half* Kg = g_K + ((size_t)bh * SEQ + t0) * DDIM;
        #pragma unroll
        for (int it = 0; it < 2; ++it) {
            int idx = tid + it * 512;
            int r = idx >> 3, c8 = (idx & 7) * 8;
            *(uint4*)&Ks[r][c8] = *(const uint4*)(Kg + (size_t)r * DDIM + c8);
        }
        __syncthreads();

        uint32_t acc[2][4][2];
        #pragma unroll
        for (int mi = 0; mi < 2; ++mi)
            #pragma unroll
            for (int ni = 0; ni < 4; ++ni) { acc[mi][ni][0] = 0u; acc[mi][ni][1] = 0u; }

        #pragma unroll
        for (int kk = 0; kk < 64; kk += 16) {
            uint32_t a[2][4], b[2][4];
            #pragma unroll
            for (int mi = 0; mi < 2; ++mi)
                ldsm_x4(arb[mi] + kk * 2, a[mi]);
            #pragma unroll
            for (int nj = 0; nj < 2; ++nj)
                ldsm_x4(brb[nj] + kk * 2, b[nj]);
            #pragma unroll
            for (int mi = 0; mi < 2; ++mi)
                #pragma unroll
                for (int ni = 0; ni < 4; ++ni)
                    mma16816h(acc[mi][ni], a[mi], &b[ni >> 1][(ni & 1) * 2]);
        }

        __syncthreads();   // Ks reads done; SF may overwrite

        #pragma unroll
        for (int h = 0; h < 2; ++h) {
            if ((warp_m >> 1) == h) {
                const int rbase = (warp_m & 1) * 32;
                #pragma unroll
                for (int ni = 0; ni < 4; ++ni) {
                    const int cl = warp_n * 32 + ni * 8 + t4 * 2;
                    #pragma unroll
                    for (int mi = 0; mi < 2; ++mi) {
                        #pragma unroll
                        for (int rr = 0; rr < 2; ++rr) {
                            const int rl = rbase + mi * 16 + g + rr * 8;
                            __half2 hv = *(__half2*)&acc[mi][ni][rr];
                            SF[rl][cl]     = __low2float(hv);
                            SF[rl][cl + 1] = __high2float(hv);
                        }
                    }
                }
            }
            __syncthreads();
            #pragma unroll
            for (int it = 0; it < 4; ++it) {
                int idx = tid + it * 512;
                int r = idx >> 5, c16 = (idx & 31) * 4;
                int row = s0 + h * 64 + r;
                int4 mv = *(const int4*)(amask + bidx * SEQ + t0 + c16);
                float4 v = *(const float4*)&SF[r][c16];
                float p;
                p = (float)mv.x; v.x = (v.x * p - (1.f - p) * MASKV - ((t0 + c16     < row) ? MASKV : 0.f)) * 0.125f;
                p = (float)mv.y; v.y = (v.y * p - (1.f - p) * MASKV - ((t0 + c16 + 1 < row) ? MASKV : 0.f)) * 0.125f;
                p = (float)mv.z; v.z = (v.z * p - (1.f - p) * MASKV - ((t0 + c16 + 2 < row) ? MASKV : 0.f)) * 0.125f;
                p = (float)mv.w; v.w = (v.w * p - (1.f - p) * MASKV - ((t0 + c16 + 3 < row) ? MASKV : 0.f)) * 0.125f;
                stcs128(out + ((size_t)bh * SEQ + row) * SEQ + t0 + c16, v);
            }
            if (h == 0) __syncthreads();
        }
    }
}

extern "C" void kernel_launch(void* const* d_in, const int* in_sizes, int n_in,
                              void* d_out, int out_size) {
    (void)in_sizes; (void)n_in; (void)out_size;
    const float* enc  = (const float*)d_in[0];
    const int*   am   = (const int*)d_in[2];
    const float* W    = (const float*)d_in[3];
    const float* bias = (const float*)d_in[4];
    float* out = (float*)d_out;

    __half* ench; cudaGetSymbolAddress((void**)&ench, g_ench);
    __half* Wt;   cudaGetSymbolAddress((void**)&Wt,   g_Wt);
    float2* rope; cudaGetSymbolAddress((void**)&rope, g_rope);

    cudaFuncSetAttribute(gemm1_rope, cudaFuncAttributeMaxDynamicSharedMemorySize, G1_DYN);
    cudaFuncSetAttribute(gemm2_mask, cudaFuncAttributeMaxDynamicSharedMemorySize, G2_DYN);

    prep_all<<<PREP_BLKS, 256>>>(enc, ench, W, Wt, rope);

    dim3 g1(64, NUM_TAGS);
    gemm1_rope<<<g1, 256, G1_DYN>>>(bias, am, out);

    dim3 g2(4, BATCH * NUM_TAGS);
    gemm2_mask<<<g2, 512, G2_DYN>>>(am, out);
}

// round 17
// speedup vs baseline: 1.3800x; 1.1072x over previous
#include <cuda_runtime.h>
#include <cuda_fp16.h>
#include <cstdint>

#define NUM_TAGS 9
#define DDIM 64
#define HID 768
#define SEQ 512
#define BATCH 16
#define NQK (NUM_TAGS * 2 * DDIM)   /* 1152 */
#define MASKV 1e12f

// Scratch (fp16 everywhere)
__device__ __half g_Q[(size_t)BATCH * NUM_TAGS * SEQ * DDIM];
__device__ __half g_K[(size_t)BATCH * NUM_TAGS * SEQ * DDIM];
__device__ __half g_ench[(size_t)BATCH * SEQ * HID];
__device__ __half g_Wt[(size_t)NQK * HID];                       // W^T [n][k]
__device__ float2 g_rope[SEQ * 32];                              // (sin,cos) per (s,pair)

__device__ __forceinline__ uint32_t smem_u32(const void* p) {
    uint32_t a;
    asm("{ .reg .u64 t; cvta.to.shared.u64 t, %1; cvt.u32.u64 %0, t; }" : "=r"(a) : "l"(p));
    return a;
}
__device__ __forceinline__ void cpasync16s(uint32_t saddr, const void* g) {
    asm volatile("cp.async.cg.shared.global [%0], [%1], 16;\n" :: "r"(saddr), "l"(g));
}
#define CP_COMMIT() asm volatile("cp.async.commit_group;\n")
#define SW128(o) ((o) ^ (((o) >> 3) & 0x70))

__device__ __forceinline__ void mma16816h(uint32_t* c, const uint32_t* a, const uint32_t* b) {
    asm volatile(
        "mma.sync.aligned.m16n8k16.row.col.f16.f16.f16.f16 "
        "{%0,%1}, {%2,%3,%4,%5}, {%6,%7}, {%0,%1};\n"
        : "+r"(c[0]), "+r"(c[1])
        : "r"(a[0]), "r"(a[1]), "r"(a[2]), "r"(a[3]), "r"(b[0]), "r"(b[1]));
}
__device__ __forceinline__ void ldsm_x4(uint32_t addr, uint32_t* r) {
    asm volatile("ldmatrix.sync.aligned.m8n8.x4.shared.b16 {%0,%1,%2,%3}, [%4];"
        : "=r"(r[0]), "=r"(r[1]), "=r"(r[2]), "=r"(r[3]) : "r"(addr));
}
__device__ __forceinline__ void stcs128(float* g, float4 v) {
    asm volatile("st.global.cs.v4.f32 [%0], {%1,%2,%3,%4};"
        :: "l"(g), "f"(v.x), "f"(v.y), "f"(v.z), "f"(v.w) : "memory");
}

// ===================== Merged prep kernel =====================
// blocks [0,1536): enc fp32->fp16 (MLP-2 grid-stride) ; [1536,1752): W tiles ; rest: rope
__global__ __launch_bounds__(256) void prep_all(
    const float* __restrict__ enc, __half* __restrict__ ench,
    const float* __restrict__ W, __half* __restrict__ Wt,
    float2* __restrict__ rope)
{
    __shared__ __half t[64][72];
    const int b = blockIdx.x;
    const int tid = threadIdx.x;

    if (b < 1536) {
        const int NV = BATCH * SEQ * HID / 4;          // 1,572,864 float4s
        const int STRIDE = 1536 * 256;                  // 393,216
        // 4 chunks total; process as 2 iterations of 2 independent loads
        int i0 = b * 256 + tid;
        #pragma unroll
        for (int it = 0; it < 2; ++it) {
            int ia = i0 + (2 * it) * STRIDE;
            int ib = i0 + (2 * it + 1) * STRIDE;
            float4 va = *(const float4*)(enc + (size_t)ia * 4);
            float4 vb = *(const float4*)(enc + (size_t)ib * 4);
            __half2 a0 = __floats2half2_rn(va.x, va.y);
            __half2 a1 = __floats2half2_rn(va.z, va.w);
            __half2 b0 = __floats2half2_rn(vb.x, vb.y);
            __half2 b1 = __floats2half2_rn(vb.z, vb.w);
            uint2 oa = { *(unsigned*)&a0, *(unsigned*)&a1 };
            uint2 ob = { *(unsigned*)&b0, *(unsigned*)&b1 };
            *(uint2*)(ench + (size_t)ia * 4) = oa;
            *(uint2*)(ench + (size_t)ib * 4) = ob;
        }
    } else if (b < 1536 + 216) {
        const int w = b - 1536;
        const int kb = (w % 12) * 64, nb = (w / 12) * 64;
        #pragma unroll
        for (int it = 0; it < 4; ++it) {
            int idx = tid + it * 256;
            int r = idx >> 4, c4 = (idx & 15) * 4;
            float4 v = *(const float4*)(W + (size_t)(kb + r) * NQK + nb + c4);
            t[c4 + 0][r] = __float2half_rn(v.x);
            t[c4 + 1][r] = __float2half_rn(v.y);
            t[c4 + 2][r] = __float2half_rn(v.z);
            t[c4 + 3][r] = __float2half_rn(v.w);
        }
        __syncthreads();
        #pragma unroll
        for (int it = 0; it < 4; ++it) {
            int idx = tid + it * 256;
            int r = idx >> 4, c4 = (idx & 15) * 4;
            *(uint2*)(Wt + (size_t)(nb + r) * HID + kb + c4) = *(uint2*)&t[r][c4];
        }
    } else {
        int i = (b - 1752) * 256 + tid;
        if (i < SEQ * 32) {
            int s = i >> 5, p = i & 31;
            const float LN1E4_OVER_32 = 0.28782313662425572f;
            float inv = expf(-(float)p * LN1E4_OVER_32);
            float sv, cv;
            sincosf((float)s * inv, &sv, &cv);
            rope[i] = make_float2(sv, cv);
        }
    }
}

// ===================== Kernel A: GEMM1 + bias + RoPE + masked-tile fill ======
// CTA tile 128(M) x 128(N = one tag). 8 warps = 2(M) x 4(N); warp tile 64x32.
// K-tile 64 (SW128), 2-stage cp.async, fp16 in / f16 acc.
#define G1_KT 64
#define G1_NT (HID / G1_KT)          /* 12 */
#define G1_ASZ (128 * 128)           /* 16KB */
#define G1_STAGE (2 * G1_ASZ)        /* 32KB */
#define G1_DYN (2 * G1_STAGE + 256)

__global__ __launch_bounds__(256, 2) void gemm1_rope(
    const float* __restrict__ bias, const int* __restrict__ amask,
    float* __restrict__ out)
{
    extern __shared__ char dyn_raw[];
    const uint32_t dsm = (smem_u32(dyn_raw) + 127) & ~127u;
    __shared__ float s_bias[128];

    const int tid  = threadIdx.x;
    const int lane = tid & 31, wid = tid >> 5;
    const int warp_m = wid & 1;
    const int warp_n = wid >> 1;
    const int g  = lane >> 2;
    const int t4 = lane & 3;

    const int m0 = blockIdx.x * 128;
    const int tag = blockIdx.y;
    const int n0 = tag * 128;

    if (tid < 128) s_bias[tid] = bias[n0 + tid];

    const __half* Ag = g_ench + (size_t)m0 * HID;
    const __half* Bg = g_Wt   + (size_t)n0 * HID;

    uint32_t acc[4][4][2];
    #pragma unroll
    for (int mi = 0; mi < 4; ++mi)
        #pragma unroll
        for (int ni = 0; ni < 4; ++ni) { acc[mi][ni][0] = 0u; acc[mi][ni][1] = 0u; }

    auto load_tile = [&](int kt, int st) {
        const int k0 = kt * G1_KT;
        const uint32_t abase = dsm + st * G1_STAGE;
        const uint32_t bbase = abase + G1_ASZ;
        #pragma unroll
        for (int i = 0; i < 4; ++i) {
            int idx = tid + i * 256;
            int r = idx >> 3, c = idx & 7;
            uint32_t off = (uint32_t)(r * 128 + c * 16);
            cpasync16s(abase + SW128(off), Ag + (size_t)r * HID + k0 + c * 8);
        }
        #pragma unroll
        for (int i = 0; i < 4; ++i) {
            int idx = tid + i * 256;
            int r = idx >> 3, c = idx & 7;
            uint32_t off = (uint32_t)(r * 128 + c * 16);
            cpasync16s(bbase + SW128(off), Bg + (size_t)r * HID + k0 + c * 8);
        }
    };

    load_tile(0, 0); CP_COMMIT();
    load_tile(1, 1); CP_COMMIT();

    // ---- Causal-masked output tile fill (independent of GEMM; DRAM idle) ----
    {
        const int cid = tag * 64 + blockIdx.x;            // 0..575
        const int ST[6] = {1, 2, 2, 3, 3, 3};
        const int TT[6] = {0, 0, 1, 0, 1, 2};
        #pragma unroll 4
        for (int k_ = 0; k_ < 24; ++k_) {
            int idx = cid * 6144 + k_ * 256 + tid;
            int tile_id = idx >> 12;
            int within = idx & 4095;
            int row = within >> 5, c4 = (within & 31) << 2;
            int bh = tile_id / 6, mt = tile_id - bh * 6;
            int bidx2 = bh / NUM_TAGS;
            int s0 = ST[mt] * 128, t0 = TT[mt] * 128;
            int4 mv = *(const int4*)(amask + bidx2 * SEQ + t0 + c4);
            float4 o;
            o.x = ((float)mv.x - 2.0f) * 1.25e11f;
            o.y = ((float)mv.y - 2.0f) * 1.25e11f;
            o.z = ((float)mv.z - 2.0f) * 1.25e11f;
            o.w = ((float)mv.w - 2.0f) * 1.25e11f;
            stcs128(out + ((size_t)bh * SEQ + s0 + row) * SEQ + t0 + c4, o);
        }
    }

    const uint32_t aK = ((lane >> 4) << 3) * 2;
    const uint32_t bK = (((lane >> 3) & 1) << 3) * 2;

    for (int kt = 0; kt < G1_NT; ++kt) {
        const int st = kt & 1;
        if (kt + 1 < G1_NT) asm volatile("cp.async.wait_group 1;\n" ::: "memory");
        else                asm volatile("cp.async.wait_group 0;\n" ::: "memory");
        __syncthreads();

        const uint32_t abase = dsm + st * G1_STAGE;
        const uint32_t bbase = abase + G1_ASZ;

        uint32_t arb[4], axv[4];
        #pragma unroll
        for (int mi = 0; mi < 4; ++mi) {
            int r = warp_m * 64 + mi * 16 + (lane & 15);
            arb[mi] = abase + r * 128;
            axv[mi] = (r & 7) << 4;
        }
        uint32_t brb[2], bxv[2];
        #pragma unroll
        for (int nj = 0; nj < 2; ++nj) {
            int n = warp_n * 32 + nj * 16 + ((lane >> 4) << 3) + (lane & 7);
            brb[nj] = bbase + n * 128;
            bxv[nj] = (n & 7) << 4;
        }

        #pragma unroll
        for (int kk2 = 0; kk2 < 128; kk2 += 32) {
            uint32_t a[4][4], b[2][4];
            #pragma unroll
            for (int mi = 0; mi < 4; ++mi)
                ldsm_x4(arb[mi] + ((kk2 + aK) ^ axv[mi]), a[mi]);
            #pragma unroll
            for (int nj = 0; nj < 2; ++nj)
                ldsm_x4(brb[nj] + ((kk2 + bK) ^ bxv[nj]), b[nj]);
            #pragma unroll
            for (int mi = 0; mi < 4; ++mi) {
                #pragma unroll
                for (int ni = 0; ni < 4; ++ni)
                    mma16816h(acc[mi][ni], a[mi], &b[ni >> 1][(ni & 1) * 2]);
            }
        }
        __syncthreads();
        if (kt + 2 < G1_NT) { load_tile(kt + 2, st); CP_COMMIT(); }
    }

    // ---- Epilogue: bias + RoPE -> fp16 Q/K ----
    #pragma unroll
    for (int ni = 0; ni < 4; ++ni) {
        const int col = warp_n * 32 + ni * 8 + t4 * 2;
        const bool isq = col < 64;
        const int dcol = col & 63;
        const float b0 = s_bias[col], b1 = s_bias[col + 1];
        __half* dstbase = isq ? g_Q : g_K;
        #pragma unroll
        for (int mi = 0; mi < 4; ++mi) {
            #pragma unroll
            for (int rr = 0; rr < 2; ++rr) {
                const int m = m0 + warp_m * 64 + mi * 16 + g + rr * 8;
                const int bb = m >> 9, s = m & 511;
                float2 sc = g_rope[s * 32 + (dcol >> 1)];
                __half2 hv = *(__half2*)&acc[mi][ni][rr];
                float v0 = __low2float(hv) + b0;
                float v1 = __high2float(hv) + b1;
                float y0 = v0 * sc.y - v1 * sc.x;
                float y1 = v1 * sc.y + v0 * sc.x;
                size_t off = (((size_t)(bb * NUM_TAGS + tag) * SEQ + s) * DDIM + dcol);
                *(__half2*)(dstbase + off) = __floats2half2_rn(y0, y1);
            }
        }
    }
}

// ===================== Kernel B: QK^T + mask + scale (upper tiles only) ======
// grid (10, 144). 512 threads, 16 warps 4x4, warp tile 32x32, ldmatrix, f16 acc,
// smem-staged coalesced epilogue with streaming stores.
__global__ __launch_bounds__(512, 2) void gemm2_mask(
    const int* __restrict__ amask, float* __restrict__ out)
{
    const int ST2[10] = {0, 1, 2, 3, 0, 0, 0, 1, 1, 2};
    const int TT2[10] = {0, 1, 2, 3, 1, 2, 3, 2, 3, 3};
    const int st = ST2[blockIdx.x], tt = TT2[blockIdx.x];
    const int bh = blockIdx.y;
    const int bidx = bh / NUM_TAGS;
    const int t0 = tt * 128, s0 = st * 128;
    const int tid = threadIdx.x;

    __shared__ __align__(16) char sraw[36864];
    __half (*Qs)[72] = (__half (*)[72])sraw;
    __half (*Ks)[72] = (__half (*)[72])(sraw + 18432);
    float (*SF)[132] = (float (*)[132])sraw;

    const __half* Qg = g_Q + ((size_t)bh * SEQ + s0) * DDIM;
    const __half* Kg = g_K + ((size_t)bh * SEQ + t0) * DDIM;
    #pragma unroll
    for (int it = 0; it < 2; ++it) {
        int idx = tid + it * 512;
        int r = idx >> 3, c8 = (idx & 7) * 8;
        *(uint4*)&Qs[r][c8] = *(const uint4*)(Qg + (size_t)r * DDIM + c8);
        *(uint4*)&Ks[r][c8] = *(const uint4*)(Kg + (size_t)r * DDIM + c8);
    }
    __syncthreads();

    const int lane = tid & 31, wid = tid >> 5;
    const int warp_m = wid & 3, warp_n = wid >> 2;
    const int g = lane >> 2, t4 = lane & 3;

    uint32_t acc[2][4][2];
    #pragma unroll
    for (int mi = 0; mi < 2; ++mi)
        #pragma unroll
        for (int ni = 0; ni < 4; ++ni) { acc[mi][ni][0] = 0u; acc[mi][ni][1] = 0u; }

    const uint32_t qbase = smem_u32(&Qs[0][0]);
    const uint32_t kbase = smem_u32(&Ks[0][0]);
    uint32_t arb[2], brb[2];
    #pragma unroll
    for (int mi = 0; mi < 2; ++mi) {
        int r = warp_m * 32 + mi * 16 + (lane & 15);
        arb[mi] = qbase + r * 144 + ((lane >> 4) << 4);
    }
    #pragma unroll
    for (int nj = 0; nj < 2; ++nj) {
        int n = warp_n * 32 + nj * 16 + ((lane >> 4) << 3) + (lane & 7);
        brb[nj] = kbase + n * 144 + (((lane >> 3) & 1) << 4);
    }

    #pragma unroll
    for (int kk = 0; kk < 64; kk += 16) {
        uint32_t a[2][4], b[2][4];
        #pragma unroll
        for (int mi = 0; mi < 2; ++mi)
            ldsm_x4(arb[mi] + kk * 2, a[mi]);
        #pragma unroll
        for (int nj = 0; nj < 2; ++nj)
            ldsm_x4(brb[nj] + kk * 2, b[nj]);
        #pragma unroll
        for (int mi = 0; mi < 2; ++mi)
            #pragma unroll
            for (int ni = 0; ni < 4; ++ni)
                mma16816h(acc[mi][ni], a[mi], &b[ni >> 1][(ni & 1) * 2]);
    }

    __syncthreads();

    #pragma unroll
    for (int h = 0; h < 2; ++h) {
        if ((warp_m >> 1) == h) {
            const int rbase = (warp_m & 1) * 32;
            #pragma unroll
            for (int ni = 0; ni < 4; ++ni) {
                const int cl = warp_n * 32 + ni * 8 + t4 * 2;
                #pragma unroll
                for (int mi = 0; mi < 2; ++mi) {
                    #pragma unroll
                    for (int rr = 0; rr < 2; ++rr) {
                        const int rl = rbase + mi * 16 + g + rr * 8;
                        __half2 hv = *(__half2*)&acc[mi][ni][rr];
                        SF[rl][cl]     = __low2float(hv);
                        SF[rl][cl + 1] = __high2float(hv);
                    }
                }
            }
        }
        __syncthreads();
        #pragma unroll
        for (int it = 0; it < 4; ++it) {
            int idx = tid + it * 512;
            int r = idx >> 5, c16 = (idx & 31) * 4;
            int row = s0 + h * 64 + r;
            int4 mv = *(const int4*)(amask + bidx * SEQ + t0 + c16);
            float4 v = *(const float4*)&SF[r][c16];
            float p;
            p = (float)mv.x; v.x = (v.x * p - (1.f - p) * MASKV - ((t0 + c16     < row) ? MASKV : 0.f)) * 0.125f;
            p = (float)mv.y; v.y = (v.y * p - (1.f - p) * MASKV - ((t0 + c16 + 1 < row) ? MASKV : 0.f)) * 0.125f;
            p = (float)mv.z; v.z = (v.z * p - (1.f - p) * MASKV - ((t0 + c16 + 2 < row) ? MASKV : 0.f)) * 0.125f;
            p = (float)mv.w; v.w = (v.w * p - (1.f - p) * MASKV - ((t0 + c16 + 3 < row) ? MASKV : 0.f)) * 0.125f;
            stcs128(out + ((size_t)bh * SEQ + row) * SEQ + t0 + c16, v);
        }
        if (h == 0) __syncthreads();
    }
}

extern "C" void kernel_launch(void* const* d_in, const int* in_sizes, int n_in,
                              void* d_out, int out_size) {
    (void)in_sizes; (void)n_in; (void)out_size;
    const float* enc  = (const float*)d_in[0];
    const int*   am   = (const int*)d_in[2];
    const float* W    = (const float*)d_in[3];
    const float* bias = (const float*)d_in[4];
    float* out = (float*)d_out;

    __half* ench; cudaGetSymbolAddress((void**)&ench, g_ench);
    __half* Wt;   cudaGetSymbolAddress((void**)&Wt,   g_Wt);
    float2* rope; cudaGetSymbolAddress((void**)&rope, g_rope);

    cudaFuncSetAttribute(gemm1_rope, cudaFuncAttributeMaxDynamicSharedMemorySize, G1_DYN);

    prep_all<<<1816, 256>>>(enc, ench, W, Wt, rope);

    dim3 g1(64, NUM_TAGS);
    gemm1_rope<<<g1, 256, G1_DYN>>>(bias, am, out);

    dim3 g2(10, BATCH * NUM_TAGS);
    gemm2_mask<<<g2, 512>>>(am, out);
}